// round 12
// baseline (speedup 1.0000x reference)
#include <cuda_runtime.h>

#define NWARPS 8
#define NTHREADS 256
#define D 256
#define F4_PER_ROW (D/4)
#define MAX_PART4 4096            // up to 16384 block partials (float4-packed)

__device__ float4       g_part4[MAX_PART4];   // zero-initialized .bss
__device__ unsigned int g_ticket = 0;         // reset by last block (replayable)

__device__ __forceinline__ float dot4(float4 a, float4 b) {
    return fmaf(a.x, b.x, fmaf(a.y, b.y, fmaf(a.z, b.z, a.w * b.w)));
}

__device__ __forceinline__ void butterfly10(float v[10]) {
    #pragma unroll
    for (int off = 16; off > 0; off >>= 1) {
        #pragma unroll
        for (int k = 0; k < 10; k++)
            v[k] += __shfl_xor_sync(0xFFFFFFFFu, v[k], off);
    }
}

// Lanes 0..3 each evaluate one anchor's weighted 3-way log-softmax; others 0.
__device__ __forceinline__ float softmax_acc(const float v[10], int lane,
                                             const float* __restrict__ sl) {
    if (lane >= 4) return 0.0f;

    float r0 = rsqrtf(fmaxf(v[0], 1e-16f));
    float r1 = rsqrtf(fmaxf(v[1], 1e-16f));
    float r2 = rsqrtf(fmaxf(v[2], 1e-16f));
    float r3 = rsqrtf(fmaxf(v[3], 1e-16f));

    float s01 = v[4] * (r0 * r1);
    float s02 = v[5] * (r0 * r2);
    float s03 = v[6] * (r0 * r3);
    float s12 = v[7] * (r1 * r2);
    float s13 = v[8] * (r1 * r3);
    float s23 = v[9] * (r2 * r3);

    // anchor i logits (pos, neg0, neg1):
    // i=0:(s02,s01,s03) i=1:(s13,s01,s12) i=2:(s02,s12,s23) i=3:(s13,s03,s23)
    float p  = (lane & 1)  ? s13 : s02;
    float n0 = (lane < 2)  ? s01 : ((lane == 2) ? s12 : s03);
    float n1 = (lane == 0) ? s03 : ((lane == 1) ? s12 : s23);

    const float invT = 2.0f;  // 1/TEMPERATURE, T = 0.5
    float l0 = p * invT, l1 = n0 * invT, l2 = n1 * invT;

    float m   = fmaxf(l0, fmaxf(l1, l2));
    float e   = __expf(l0 - m) + __expf(l1 - m) + __expf(l2 - m);
    float lse = m + __logf(e);

    float w0 = __ldg(sl + lane * 3 + 0);
    float w1 = __ldg(sl + lane * 3 + 1);
    float w2 = __ldg(sl + lane * 3 + 2);

    return (lse - l0) * w0 + (lse - l1) * w1 + (lse - l2) * w2;
}

// minBlocks=5 -> 51-reg cap: keeps the ticket epilogue from inflating the
// register allocation and losing the 5th resident CTA (R11 lesson).
__global__ __launch_bounds__(NTHREADS, 5)
void ntxent_kernel(const float* __restrict__ zis,
                   const float* __restrict__ zjs,
                   const float* __restrict__ soft_labels,
                   float* __restrict__ out,
                   int nc)
{
    __shared__ float wsum[NWARPS];
    __shared__ bool  is_last;

    const int tid  = threadIdx.x;
    const int warp = tid >> 5;
    const int lane = tid & 31;

    // One group per warp, one-shot CTA — HW CTA replacement provides the
    // cross-group load/compute overlap (empirically the best config: R4).
    const int g = blockIdx.x * NWARPS + warp;

    float acc = 0.0f;
    if (g < nc) {
        const float4* pj = reinterpret_cast<const float4*>(zjs) + (size_t)g * (2 * F4_PER_ROW);
        const float4* pi = reinterpret_cast<const float4*>(zis) + (size_t)g * (2 * F4_PER_ROW);

        // Front-batched: 8 independent LDG.128 per lane
        float4 a0 = pj[lane];       float4 a1 = pj[lane + 32];
        float4 b0 = pj[lane + 64];  float4 b1 = pj[lane + 96];
        float4 c0 = pi[lane];       float4 c1 = pi[lane + 32];
        float4 d0 = pi[lane + 64];  float4 d1 = pi[lane + 96];

        float v[10];
        v[0] = dot4(a0, a0) + dot4(a1, a1);
        v[1] = dot4(b0, b0) + dot4(b1, b1);
        v[2] = dot4(c0, c0) + dot4(c1, c1);
        v[3] = dot4(d0, d0) + dot4(d1, d1);
        v[4] = dot4(a0, b0) + dot4(a1, b1);
        v[5] = dot4(a0, c0) + dot4(a1, c1);
        v[6] = dot4(a0, d0) + dot4(a1, d1);
        v[7] = dot4(b0, c0) + dot4(b1, c1);
        v[8] = dot4(b0, d0) + dot4(b1, d1);
        v[9] = dot4(c0, d0) + dot4(c1, d1);

        butterfly10(v);
        acc += softmax_acc(v, lane, soft_labels);
    }

    // fold lanes 0..3 -> lane 0
    acc += __shfl_xor_sync(0xFFFFFFFFu, acc, 1);
    acc += __shfl_xor_sync(0xFFFFFFFFu, acc, 2);
    if (lane == 0) wsum[warp] = acc;
    __syncthreads();

    // block partial -> scratch; last block finishes (no memset node needed)
    if (tid == 0) {
        float t = 0.0f;
        #pragma unroll
        for (int w = 0; w < NWARPS; w++) t += wsum[w];
        reinterpret_cast<float*>(g_part4)[blockIdx.x] = t;
        __threadfence();
        unsigned old = atomicAdd(&g_ticket, 1u);
        is_last = (old == (unsigned)(gridDim.x - 1));
    }
    __syncthreads();

    if (is_last) {
        __threadfence();
        // Reduce gridDim.x partials, float4-packed (4096 -> 1024 float4).
        const int n4 = (int)(gridDim.x + 3) >> 2;
        float t = 0.0f;
        for (int i = tid; i < n4; i += NTHREADS) {
            float4 p = g_part4[i];
            t += (p.x + p.y) + (p.z + p.w);
        }
        #pragma unroll
        for (int off = 16; off > 0; off >>= 1)
            t += __shfl_xor_sync(0xFFFFFFFFu, t, off);
        if (lane == 0) wsum[warp] = t;
        __syncthreads();
        if (tid == 0) {
            float tot = 0.0f;
            #pragma unroll
            for (int w = 0; w < NWARPS; w++) tot += wsum[w];
            out[0] = tot * (1.0f / (4.0f * (float)nc));  // 1/(2n)
            g_ticket = 0;   // reset for graph replay
        }
    }
}

extern "C" void kernel_launch(void* const* d_in, const int* in_sizes, int n_in,
                              void* d_out, int out_size)
{
    const float* zis = (const float*)d_in[0];
    const float* zjs = (const float*)d_in[1];
    const float* sl  = (const float*)d_in[2];
    float* out = (float*)d_out;

    int n  = in_sizes[0] / D;   // 65536 rows
    int nc = n / 2;             // 32768 groups

    int blocks = (nc + NWARPS - 1) / NWARPS;   // 4096
    ntxent_kernel<<<blocks, NTHREADS>>>(zis, zjs, sl, out, nc);
}

// round 13
// speedup vs baseline: 1.2294x; 1.2294x over previous
#include <cuda_runtime.h>

#define NWARPS 8
#define NTHREADS 256
#define D 256
#define F4_PER_ROW (D/4)

__device__ float        g_sum    = 0.0f;   // global accumulator (.bss zero-init)
__device__ unsigned int g_ticket = 0;      // reset by last block (replayable)

__device__ __forceinline__ float dot4(float4 a, float4 b) {
    return fmaf(a.x, b.x, fmaf(a.y, b.y, fmaf(a.z, b.z, a.w * b.w)));
}

__device__ __forceinline__ void butterfly10(float v[10]) {
    #pragma unroll
    for (int off = 16; off > 0; off >>= 1) {
        #pragma unroll
        for (int k = 0; k < 10; k++)
            v[k] += __shfl_xor_sync(0xFFFFFFFFu, v[k], off);
    }
}

// Lanes 0..3 each evaluate one anchor's weighted 3-way log-softmax; others 0.
__device__ __forceinline__ float softmax_acc(const float v[10], int lane,
                                             const float* __restrict__ sl) {
    if (lane >= 4) return 0.0f;

    float r0 = rsqrtf(fmaxf(v[0], 1e-16f));
    float r1 = rsqrtf(fmaxf(v[1], 1e-16f));
    float r2 = rsqrtf(fmaxf(v[2], 1e-16f));
    float r3 = rsqrtf(fmaxf(v[3], 1e-16f));

    float s01 = v[4] * (r0 * r1);
    float s02 = v[5] * (r0 * r2);
    float s03 = v[6] * (r0 * r3);
    float s12 = v[7] * (r1 * r2);
    float s13 = v[8] * (r1 * r3);
    float s23 = v[9] * (r2 * r3);

    // anchor i logits (pos, neg0, neg1):
    // i=0:(s02,s01,s03) i=1:(s13,s01,s12) i=2:(s02,s12,s23) i=3:(s13,s03,s23)
    float p  = (lane & 1)  ? s13 : s02;
    float n0 = (lane < 2)  ? s01 : ((lane == 2) ? s12 : s03);
    float n1 = (lane == 0) ? s03 : ((lane == 1) ? s12 : s23);

    const float invT = 2.0f;  // 1/TEMPERATURE, T = 0.5
    float l0 = p * invT, l1 = n0 * invT, l2 = n1 * invT;

    float m   = fmaxf(l0, fmaxf(l1, l2));
    float e   = __expf(l0 - m) + __expf(l1 - m) + __expf(l2 - m);
    float lse = m + __logf(e);

    float w0 = __ldg(sl + lane * 3 + 0);
    float w1 = __ldg(sl + lane * 3 + 1);
    float w2 = __ldg(sl + lane * 3 + 2);

    return (lse - l0) * w0 + (lse - l1) * w1 + (lse - l2) * w2;
}

__global__ __launch_bounds__(NTHREADS, 5)
void ntxent_kernel(const float* __restrict__ zis,
                   const float* __restrict__ zjs,
                   const float* __restrict__ soft_labels,
                   float* __restrict__ out,
                   int nc)
{
    __shared__ float wsum[NWARPS];

    const int tid  = threadIdx.x;
    const int warp = tid >> 5;
    const int lane = tid & 31;

    // One group per warp, one-shot CTA — HW CTA replacement provides the
    // cross-group load/compute overlap (empirically the best config: R4).
    const int g = blockIdx.x * NWARPS + warp;

    float acc = 0.0f;
    if (g < nc) {
        const float4* pj = reinterpret_cast<const float4*>(zjs) + (size_t)g * (2 * F4_PER_ROW);
        const float4* pi = reinterpret_cast<const float4*>(zis) + (size_t)g * (2 * F4_PER_ROW);

        // Front-batched: 8 independent LDG.128 per lane
        float4 a0 = pj[lane];       float4 a1 = pj[lane + 32];
        float4 b0 = pj[lane + 64];  float4 b1 = pj[lane + 96];
        float4 c0 = pi[lane];       float4 c1 = pi[lane + 32];
        float4 d0 = pi[lane + 64];  float4 d1 = pi[lane + 96];

        float v[10];
        v[0] = dot4(a0, a0) + dot4(a1, a1);
        v[1] = dot4(b0, b0) + dot4(b1, b1);
        v[2] = dot4(c0, c0) + dot4(c1, c1);
        v[3] = dot4(d0, d0) + dot4(d1, d1);
        v[4] = dot4(a0, b0) + dot4(a1, b1);
        v[5] = dot4(a0, c0) + dot4(a1, c1);
        v[6] = dot4(a0, d0) + dot4(a1, d1);
        v[7] = dot4(b0, c0) + dot4(b1, c1);
        v[8] = dot4(b0, d0) + dot4(b1, d1);
        v[9] = dot4(c0, d0) + dot4(c1, d1);

        butterfly10(v);
        acc += softmax_acc(v, lane, soft_labels);
    }

    // fold lanes 0..3 -> lane 0
    acc += __shfl_xor_sync(0xFFFFFFFFu, acc, 1);
    acc += __shfl_xor_sync(0xFFFFFFFFu, acc, 2);
    if (lane == 0) wsum[warp] = acc;
    __syncthreads();

    // Near-zero-register finish: one global atomicAdd per block + ticket.
    if (tid == 0) {
        float t = 0.0f;
        #pragma unroll
        for (int w = 0; w < NWARPS; w++) t += wsum[w];
        atomicAdd(&g_sum, t);
        __threadfence();
        unsigned old = atomicAdd(&g_ticket, 1u);
        if (old == (unsigned)(gridDim.x - 1)) {
            __threadfence();
            float tot = *((volatile float*)&g_sum);
            out[0] = tot * (1.0f / (4.0f * (float)nc));  // 1/(2n)
            *((volatile float*)&g_sum) = 0.0f;           // reset for replay
            __threadfence();
            *((volatile unsigned int*)&g_ticket) = 0u;
        }
    }
}

extern "C" void kernel_launch(void* const* d_in, const int* in_sizes, int n_in,
                              void* d_out, int out_size)
{
    const float* zis = (const float*)d_in[0];
    const float* zjs = (const float*)d_in[1];
    const float* sl  = (const float*)d_in[2];
    float* out = (float*)d_out;

    int n  = in_sizes[0] / D;   // 65536 rows
    int nc = n / 2;             // 32768 groups

    int blocks = (nc + NWARPS - 1) / NWARPS;   // 4096
    ntxent_kernel<<<blocks, NTHREADS>>>(zis, zjs, sl, out, nc);
}

// round 14
// speedup vs baseline: 1.2308x; 1.0011x over previous
#include <cuda_runtime.h>

#define NWARPS 8
#define NTHREADS 256
#define D 256
#define F4_PER_ROW (D/4)

__device__ float        g_sum    = 0.0f;   // global accumulator (.bss zero-init)
__device__ unsigned int g_ticket = 0;      // reset by last block (replayable)

__device__ __forceinline__ float dot4(float4 a, float4 b) {
    return fmaf(a.x, b.x, fmaf(a.y, b.y, fmaf(a.z, b.z, a.w * b.w)));
}

__device__ __forceinline__ void butterfly10(float v[10]) {
    #pragma unroll
    for (int off = 16; off > 0; off >>= 1) {
        #pragma unroll
        for (int k = 0; k < 10; k++)
            v[k] += __shfl_xor_sync(0xFFFFFFFFu, v[k], off);
    }
}

// Lanes 0..3 each evaluate one anchor's weighted 3-way log-softmax; others 0.
__device__ __forceinline__ float softmax_acc(const float v[10], int lane,
                                             const float* __restrict__ sl) {
    if (lane >= 4) return 0.0f;

    float r0 = rsqrtf(fmaxf(v[0], 1e-16f));
    float r1 = rsqrtf(fmaxf(v[1], 1e-16f));
    float r2 = rsqrtf(fmaxf(v[2], 1e-16f));
    float r3 = rsqrtf(fmaxf(v[3], 1e-16f));

    float s01 = v[4] * (r0 * r1);
    float s02 = v[5] * (r0 * r2);
    float s03 = v[6] * (r0 * r3);
    float s12 = v[7] * (r1 * r2);
    float s13 = v[8] * (r1 * r3);
    float s23 = v[9] * (r2 * r3);

    // anchor i logits (pos, neg0, neg1):
    // i=0:(s02,s01,s03) i=1:(s13,s01,s12) i=2:(s02,s12,s23) i=3:(s13,s03,s23)
    float p  = (lane & 1)  ? s13 : s02;
    float n0 = (lane < 2)  ? s01 : ((lane == 2) ? s12 : s03);
    float n1 = (lane == 0) ? s03 : ((lane == 1) ? s12 : s23);

    const float invT = 2.0f;  // 1/TEMPERATURE, T = 0.5
    float l0 = p * invT, l1 = n0 * invT, l2 = n1 * invT;

    float m   = fmaxf(l0, fmaxf(l1, l2));
    float e   = __expf(l0 - m) + __expf(l1 - m) + __expf(l2 - m);
    float lse = m + __logf(e);

    float w0 = __ldg(sl + lane * 3 + 0);
    float w1 = __ldg(sl + lane * 3 + 1);
    float w2 = __ldg(sl + lane * 3 + 2);

    return (lse - l0) * w0 + (lse - l1) * w1 + (lse - l2) * w2;
}

// R4's exact compilation conditions: minBlocks=4. The lb5 variant (R13)
// changed ptxas scheduling and lost the front-batched MLP (DRAM 72.7->60.6%).
__global__ __launch_bounds__(NTHREADS, 4)
void ntxent_kernel(const float* __restrict__ zis,
                   const float* __restrict__ zjs,
                   const float* __restrict__ soft_labels,
                   float* __restrict__ out,
                   int nc)
{
    __shared__ float wsum[NWARPS];

    const int tid  = threadIdx.x;
    const int warp = tid >> 5;
    const int lane = tid & 31;

    // One group per warp, one-shot CTA — HW CTA replacement provides the
    // cross-group load/compute overlap (empirically the best config: R4).
    const int g = blockIdx.x * NWARPS + warp;

    float acc = 0.0f;
    if (g < nc) {
        const float4* pj = reinterpret_cast<const float4*>(zjs) + (size_t)g * (2 * F4_PER_ROW);
        const float4* pi = reinterpret_cast<const float4*>(zis) + (size_t)g * (2 * F4_PER_ROW);

        // Front-batched: 8 independent LDG.128 per lane
        float4 a0 = pj[lane];       float4 a1 = pj[lane + 32];
        float4 b0 = pj[lane + 64];  float4 b1 = pj[lane + 96];
        float4 c0 = pi[lane];       float4 c1 = pi[lane + 32];
        float4 d0 = pi[lane + 64];  float4 d1 = pi[lane + 96];

        float v[10];
        v[0] = dot4(a0, a0) + dot4(a1, a1);
        v[1] = dot4(b0, b0) + dot4(b1, b1);
        v[2] = dot4(c0, c0) + dot4(c1, c1);
        v[3] = dot4(d0, d0) + dot4(d1, d1);
        v[4] = dot4(a0, b0) + dot4(a1, b1);
        v[5] = dot4(a0, c0) + dot4(a1, c1);
        v[6] = dot4(a0, d0) + dot4(a1, d1);
        v[7] = dot4(b0, c0) + dot4(b1, c1);
        v[8] = dot4(b0, d0) + dot4(b1, d1);
        v[9] = dot4(c0, d0) + dot4(c1, d1);

        butterfly10(v);
        acc += softmax_acc(v, lane, soft_labels);
    }

    // fold lanes 0..3 -> lane 0
    acc += __shfl_xor_sync(0xFFFFFFFFu, acc, 1);
    acc += __shfl_xor_sync(0xFFFFFFFFu, acc, 2);
    if (lane == 0) wsum[warp] = acc;
    __syncthreads();

    // Near-zero-register finish: one global atomicAdd per block + ticket.
    if (tid == 0) {
        float t = 0.0f;
        #pragma unroll
        for (int w = 0; w < NWARPS; w++) t += wsum[w];
        atomicAdd(&g_sum, t);
        __threadfence();
        unsigned old = atomicAdd(&g_ticket, 1u);
        if (old == (unsigned)(gridDim.x - 1)) {
            __threadfence();
            float tot = *((volatile float*)&g_sum);
            out[0] = tot * (1.0f / (4.0f * (float)nc));  // 1/(2n)
            *((volatile float*)&g_sum) = 0.0f;           // reset for replay
            __threadfence();
            *((volatile unsigned int*)&g_ticket) = 0u;
        }
    }
}

extern "C" void kernel_launch(void* const* d_in, const int* in_sizes, int n_in,
                              void* d_out, int out_size)
{
    const float* zis = (const float*)d_in[0];
    const float* zjs = (const float*)d_in[1];
    const float* sl  = (const float*)d_in[2];
    float* out = (float*)d_out;

    int n  = in_sizes[0] / D;   // 65536 rows
    int nc = n / 2;             // 32768 groups

    int blocks = (nc + NWARPS - 1) / NWARPS;   // 4096
    ntxent_kernel<<<blocks, NTHREADS>>>(zis, zjs, sl, out, nc);
}

// round 15
// speedup vs baseline: 1.2897x; 1.0479x over previous
#include <cuda_runtime.h>

#define NWARPS 8
#define NTHREADS 256
#define D 256
#define F4_PER_ROW (D/4)

__device__ float        g_sum    = 0.0f;   // global accumulator (.bss zero-init)
__device__ unsigned int g_ticket = 0;      // reset by last block (replayable)

__device__ __forceinline__ float dot4(float4 a, float4 b) {
    return fmaf(a.x, b.x, fmaf(a.y, b.y, fmaf(a.z, b.z, a.w * b.w)));
}

__device__ __forceinline__ void butterfly10(float v[10]) {
    #pragma unroll
    for (int off = 16; off > 0; off >>= 1) {
        #pragma unroll
        for (int k = 0; k < 10; k++)
            v[k] += __shfl_xor_sync(0xFFFFFFFFu, v[k], off);
    }
}

// Lanes 0..3 each evaluate one anchor's weighted 3-way log-softmax; others 0.
__device__ __forceinline__ float softmax_acc(const float v[10], int lane,
                                             const float* __restrict__ sl) {
    if (lane >= 4) return 0.0f;

    float r0 = rsqrtf(fmaxf(v[0], 1e-16f));
    float r1 = rsqrtf(fmaxf(v[1], 1e-16f));
    float r2 = rsqrtf(fmaxf(v[2], 1e-16f));
    float r3 = rsqrtf(fmaxf(v[3], 1e-16f));

    float s01 = v[4] * (r0 * r1);
    float s02 = v[5] * (r0 * r2);
    float s03 = v[6] * (r0 * r3);
    float s12 = v[7] * (r1 * r2);
    float s13 = v[8] * (r1 * r3);
    float s23 = v[9] * (r2 * r3);

    // anchor i logits (pos, neg0, neg1):
    // i=0:(s02,s01,s03) i=1:(s13,s01,s12) i=2:(s02,s12,s23) i=3:(s13,s03,s23)
    float p  = (lane & 1)  ? s13 : s02;
    float n0 = (lane < 2)  ? s01 : ((lane == 2) ? s12 : s03);
    float n1 = (lane == 0) ? s03 : ((lane == 1) ? s12 : s23);

    const float invT = 2.0f;  // 1/TEMPERATURE, T = 0.5
    float l0 = p * invT, l1 = n0 * invT, l2 = n1 * invT;

    float m   = fmaxf(l0, fmaxf(l1, l2));
    float e   = __expf(l0 - m) + __expf(l1 - m) + __expf(l2 - m);
    float lse = m + __logf(e);

    float w0 = __ldg(sl + lane * 3 + 0);
    float w1 = __ldg(sl + lane * 3 + 1);
    float w2 = __ldg(sl + lane * 3 + 2);

    return (lse - l0) * w0 + (lse - l1) * w1 + (lse - l2) * w2;
}

__global__ __launch_bounds__(NTHREADS, 4)
void ntxent_kernel(const float* __restrict__ zis,
                   const float* __restrict__ zjs,
                   const float* __restrict__ soft_labels,
                   float* __restrict__ out,
                   int nc)
{
    __shared__ float wsum[NWARPS];

    const int tid  = threadIdx.x;
    const int warp = tid >> 5;
    const int lane = tid & 31;

    // One group per warp, one-shot CTA — HW CTA replacement provides the
    // cross-group load/compute overlap (empirically the best config: R4).
    const int g = blockIdx.x * NWARPS + warp;

    float acc = 0.0f;
    if (g < nc) {
        const float4* pj = reinterpret_cast<const float4*>(zjs) + (size_t)g * (2 * F4_PER_ROW);
        const float4* pi = reinterpret_cast<const float4*>(zis) + (size_t)g * (2 * F4_PER_ROW);

        // Front-batched: 8 independent LDG.128 per lane
        float4 a0 = pj[lane];       float4 a1 = pj[lane + 32];
        float4 b0 = pj[lane + 64];  float4 b1 = pj[lane + 96];
        float4 c0 = pi[lane];       float4 c1 = pi[lane + 32];
        float4 d0 = pi[lane + 64];  float4 d1 = pi[lane + 96];

        float v[10];
        v[0] = dot4(a0, a0) + dot4(a1, a1);
        v[1] = dot4(b0, b0) + dot4(b1, b1);
        v[2] = dot4(c0, c0) + dot4(c1, c1);
        v[3] = dot4(d0, d0) + dot4(d1, d1);
        v[4] = dot4(a0, b0) + dot4(a1, b1);
        v[5] = dot4(a0, c0) + dot4(a1, c1);
        v[6] = dot4(a0, d0) + dot4(a1, d1);
        v[7] = dot4(b0, c0) + dot4(b1, c1);
        v[8] = dot4(b0, d0) + dot4(b1, d1);
        v[9] = dot4(c0, d0) + dot4(c1, d1);

        butterfly10(v);
        acc += softmax_acc(v, lane, soft_labels);
    }

    // fold lanes 0..3 -> lane 0
    acc += __shfl_xor_sync(0xFFFFFFFFu, acc, 1);
    acc += __shfl_xor_sync(0xFFFFFFFFu, acc, 2);
    if (lane == 0) wsum[warp] = acc;
    __syncthreads();

    // Minimal-tail finish: relaxed RED (no return) + release-atomic ticket.
    // The release on the ticket orders the g_sum add — no standalone MEMBAR,
    // no dependent atomic chain blocking CTA retirement (R14 lesson).
    if (tid == 0) {
        float t = 0.0f;
        #pragma unroll
        for (int w = 0; w < NWARPS; w++) t += wsum[w];

        asm volatile("red.relaxed.gpu.global.add.f32 [%0], %1;"
                     :: "l"(&g_sum), "f"(t) : "memory");
        unsigned old;
        asm volatile("atom.release.gpu.global.add.u32 %0, [%1], %2;"
                     : "=r"(old) : "l"(&g_ticket), "r"(1u) : "memory");

        if (old == (unsigned)(gridDim.x - 1)) {
            float tot;
            asm volatile("ld.acquire.gpu.global.f32 %0, [%1];"
                         : "=f"(tot) : "l"(&g_sum) : "memory");
            out[0] = tot * (1.0f / (4.0f * (float)nc));  // 1/(2n)
            // reset for next graph replay (kernel boundary publishes these)
            g_sum    = 0.0f;
            g_ticket = 0u;
        }
    }
}

extern "C" void kernel_launch(void* const* d_in, const int* in_sizes, int n_in,
                              void* d_out, int out_size)
{
    const float* zis = (const float*)d_in[0];
    const float* zjs = (const float*)d_in[1];
    const float* sl  = (const float*)d_in[2];
    float* out = (float*)d_out;

    int n  = in_sizes[0] / D;   // 65536 rows
    int nc = n / 2;             // 32768 groups

    int blocks = (nc + NWARPS - 1) / NWARPS;   // 4096
    ntxent_kernel<<<blocks, NTHREADS>>>(zis, zjs, sl, out, nc);
}